// round 1
// baseline (speedup 1.0000x reference)
#include <cuda_runtime.h>
#include <math.h>

// TopKRouter: logits = x @ W^T, softmax, top-2, renormalized weights.
// x: (4,4096,4096) fp32 -> 16384 tokens x 4096 dims
// W: (64,4096) fp32
// out (fp32): [indices (16384*2)][weights (16384*2)][logits (16384*64)]

#define TOKENS 16384
#define DIM    4096
#define NEXP   64
#define BT     64   // tokens per block
#define DC     64   // D-chunk

__global__ __launch_bounds__(256, 2) void router_kernel(
    const float* __restrict__ x,
    const float* __restrict__ Wg,
    float* __restrict__ out)
{
    // 32 KB shared: xs[DC][BT] then ws[DC][NEXP], reused as ls[BT][NEXP+1] in epilogue
    __shared__ float sbuf[DC * BT + DC * NEXP];
    float* xs = sbuf;            // [d][token]
    float* ws = sbuf + DC * BT;  // [d][expert]

    const int tid = threadIdx.x;
    const int tx = tid & 15;   // expert group 0..15 -> experts tx*4..tx*4+3
    const int ty = tid >> 4;   // token group 0..15  -> tokens  ty*4..ty*4+3
    const int tokBase = blockIdx.x * BT;

    float acc[4][4];
    #pragma unroll
    for (int i = 0; i < 4; i++)
        #pragma unroll
        for (int j = 0; j < 4; j++)
            acc[i][j] = 0.0f;

    for (int d0 = 0; d0 < DIM; d0 += DC) {
        // Load x chunk: 64 tokens x 64 dims, transpose into xs[d][t]
        #pragma unroll
        for (int k = 0; k < 4; k++) {
            int idx = tid + k * 256;      // 0..1023
            int d4  = idx & 15;           // float4 slot within the 64-dim chunk
            int t   = idx >> 4;           // token 0..63
            float4 v = *(const float4*)(x + (size_t)(tokBase + t) * DIM + d0 + d4 * 4);
            xs[(d4 * 4 + 0) * BT + t] = v.x;
            xs[(d4 * 4 + 1) * BT + t] = v.y;
            xs[(d4 * 4 + 2) * BT + t] = v.z;
            xs[(d4 * 4 + 3) * BT + t] = v.w;
        }
        // Load W chunk: 64 experts x 64 dims, transpose into ws[d][e]
        #pragma unroll
        for (int k = 0; k < 4; k++) {
            int idx = tid + k * 256;
            int d4  = idx & 15;
            int e   = idx >> 4;
            float4 v = *(const float4*)(Wg + (size_t)e * DIM + d0 + d4 * 4);
            ws[(d4 * 4 + 0) * NEXP + e] = v.x;
            ws[(d4 * 4 + 1) * NEXP + e] = v.y;
            ws[(d4 * 4 + 2) * NEXP + e] = v.z;
            ws[(d4 * 4 + 3) * NEXP + e] = v.w;
        }
        __syncthreads();

        #pragma unroll 8
        for (int dd = 0; dd < DC; dd++) {
            float4 a = *(const float4*)&xs[dd * BT + ty * 4];
            float4 b = *(const float4*)&ws[dd * NEXP + tx * 4];
            float av[4] = {a.x, a.y, a.z, a.w};
            float bv[4] = {b.x, b.y, b.z, b.w};
            #pragma unroll
            for (int i = 0; i < 4; i++)
                #pragma unroll
                for (int j = 0; j < 4; j++)
                    acc[i][j] = fmaf(av[i], bv[j], acc[i][j]);
        }
        __syncthreads();
    }

    // ---- epilogue: stage logits in shared (reuse sbuf), padded row of 65 ----
    float* ls = sbuf;  // [BT][NEXP+1] = 4160 floats <= 8192
    #pragma unroll
    for (int i = 0; i < 4; i++)
        #pragma unroll
        for (int j = 0; j < 4; j++)
            ls[(ty * 4 + i) * (NEXP + 1) + (tx * 4 + j)] = acc[i][j];
    __syncthreads();

    float* out_idx    = out;
    float* out_w      = out + 2 * TOKENS;
    float* out_logits = out + 4 * TOKENS;

    // Write logits to gmem (coalesced over experts)
    #pragma unroll
    for (int k = 0; k < 16; k++) {
        int idx = tid + k * 256;   // 0..4095
        int e = idx & 63;
        int t = idx >> 6;
        out_logits[(size_t)(tokBase + t) * NEXP + e] = ls[t * (NEXP + 1) + e];
    }

    // Per-token top-2 + renormalized softmax weights (64 threads, one token each)
    if (tid < BT) {
        const float* row = &ls[tid * (NEXP + 1)];
        float m1 = -INFINITY, m2 = -INFINITY;
        int i1 = 0, i2 = 0;
        #pragma unroll 8
        for (int e = 0; e < NEXP; e++) {
            float v = row[e];
            if (v > m1) { m2 = m1; i2 = i1; m1 = v; i1 = e; }
            else if (v > m2) { m2 = v; i2 = e; }
        }
        float Z = 0.0f;
        #pragma unroll 8
        for (int e = 0; e < NEXP; e++)
            Z += expf(row[e] - m1);
        float p1 = 1.0f / Z;             // exp(m1 - m1)/Z
        float p2 = expf(m2 - m1) / Z;
        float denom = p1 + p2 + 1e-9f;

        int gt = tokBase + tid;
        out_idx[gt * 2 + 0] = (float)i1;
        out_idx[gt * 2 + 1] = (float)i2;
        out_w[gt * 2 + 0] = p1 / denom;
        out_w[gt * 2 + 1] = p2 / denom;
    }
}

extern "C" void kernel_launch(void* const* d_in, const int* in_sizes, int n_in,
                              void* d_out, int out_size)
{
    const float* x  = (const float*)d_in[0];   // (4,4096,4096)
    const float* Wg = (const float*)d_in[1];   // (64,4096)
    float* out = (float*)d_out;
    router_kernel<<<TOKENS / BT, 256>>>(x, Wg, out);
}

// round 3
// speedup vs baseline: 3.5466x; 3.5466x over previous
#include <cuda_runtime.h>
#include <cuda_bf16.h>
#include <math.h>
#include <stdint.h>

// TopKRouter: logits = x @ W^T (16384x4096 @ 4096x64), softmax, top-2, renorm.
// Split-bf16 (hi/lo) 3-product mma.sync.m16n8k16 GEMM, zero smem, zero CTA sync.
// out fp32: [indices 16384*2][weights 16384*2][logits 16384*64]

#define TOKENS 16384
#define DIM    4096
#define NEXP   64
#define NKS    (DIM / 16)   // 256 k-steps

// Fragment-ordered pre-converted W: index q = ((ks*8 + nt)*32 + lane), uint2:
//   .x = bf16x2( W[n][kb], W[n][kb+1] ),  .y = bf16x2( W[n][kb+8], W[n][kb+9] )
// with n = nt*8 + lane/4, kb = ks*16 + (lane%4)*2.
__device__ uint2 g_Bh[NKS * 8 * 32];
__device__ uint2 g_Bl[NKS * 8 * 32];

// split two fp32 into bf16x2 hi (round-nearest) and bf16x2 lo (residual).
// low half of the b32 = first argument (lower k index).
__device__ __forceinline__ void split2(float a, float b, unsigned& h, unsigned& l) {
    asm("cvt.rn.bf16x2.f32 %0, %1, %2;" : "=r"(h) : "f"(b), "f"(a));
    float ha = __uint_as_float(h << 16);
    float hb = __uint_as_float(h & 0xFFFF0000u);
    float ra = a - ha;
    float rb = b - hb;
    asm("cvt.rn.bf16x2.f32 %0, %1, %2;" : "=r"(l) : "f"(rb), "f"(ra));
}

__device__ __forceinline__ void mma16816(float* c, unsigned a0, unsigned a1,
                                         unsigned a2, unsigned a3, uint2 b) {
    asm volatile(
        "mma.sync.aligned.m16n8k16.row.col.f32.bf16.bf16.f32 "
        "{%0,%1,%2,%3}, {%4,%5,%6,%7}, {%8,%9}, {%0,%1,%2,%3};"
        : "+f"(c[0]), "+f"(c[1]), "+f"(c[2]), "+f"(c[3])
        : "r"(a0), "r"(a1), "r"(a2), "r"(a3), "r"(b.x), "r"(b.y));
}

// ---------------- W pre-convert (fragment order) ----------------
__global__ void convert_w_kernel(const float* __restrict__ Wg) {
    int q = blockIdx.x * blockDim.x + threadIdx.x;   // 0..65535
    int ks   = q >> 8;
    int nt   = (q >> 5) & 7;
    int lane = q & 31;
    int n  = nt * 8 + (lane >> 2);
    int kb = ks * 16 + (lane & 3) * 2;
    const float* wr = Wg + (size_t)n * DIM + kb;
    unsigned hx, lx, hy, ly;
    split2(wr[0], wr[1], hx, lx);
    split2(wr[8], wr[9], hy, ly);
    g_Bh[q] = make_uint2(hx, hy);
    g_Bl[q] = make_uint2(lx, ly);
}

// ---------------- helpers for top-2 merge ----------------
__device__ __forceinline__ bool better(float v, int i, float v2, int i2) {
    return (v > v2) || (v == v2 && i < i2);
}

// ---------------- main kernel ----------------
__global__ __launch_bounds__(128, 2) void router_kernel(
    const float* __restrict__ x,
    float* __restrict__ out)
{
    const int tid  = threadIdx.x;
    const int wid  = tid >> 5;
    const int lane = tid & 31;
    const int tok0 = blockIdx.x * 64 + wid * 16;   // warp's 16-token tile
    const int r0   = tok0 + (lane >> 2);           // this thread's rows: r0, r0+8

    // A pointers: float2 granularity; element k0 = (lane%4)*2 within each k-step
    const float2* pA0 = (const float2*)(x + (size_t)r0 * DIM) + (lane & 3);
    const float2* pA1 = pA0 + 4 * DIM / 2 * 2;     // row r0+8 : +8*DIM floats = +4*DIM float2

    float acc[8][4];
    #pragma unroll
    for (int nt = 0; nt < 8; nt++)
        #pragma unroll
        for (int j = 0; j < 4; j++) acc[nt][j] = 0.0f;

    const uint2* __restrict__ Bh = g_Bh + lane;
    const uint2* __restrict__ Bl = g_Bl + lane;

    #pragma unroll 2
    for (int ks = 0; ks < NKS; ks++) {
        float2 v00 = __ldg(pA0 + ks * 8);          // (r0,   k0..k0+1)
        float2 v01 = __ldg(pA0 + ks * 8 + 4);      // (r0,   k0+8..)
        float2 v10 = __ldg(pA1 + ks * 8);          // (r0+8, k0..)
        float2 v11 = __ldg(pA1 + ks * 8 + 4);

        unsigned ah0, ah1, ah2, ah3, al0, al1, al2, al3;
        split2(v00.x, v00.y, ah0, al0);
        split2(v10.x, v10.y, ah1, al1);
        split2(v01.x, v01.y, ah2, al2);
        split2(v11.x, v11.y, ah3, al3);

        const uint2* bh = Bh + ks * 256;
        const uint2* bl = Bl + ks * 256;
        #pragma unroll
        for (int nt = 0; nt < 8; nt++) {
            uint2 bhv = __ldg(bh + nt * 32);
            uint2 blv = __ldg(bl + nt * 32);
            mma16816(acc[nt], ah0, ah1, ah2, ah3, bhv);   // hi * hi
            mma16816(acc[nt], ah0, ah1, ah2, ah3, blv);   // hi * lo
            mma16816(acc[nt], al0, al1, al2, al3, bhv);   // lo * hi
        }
    }

    // ---- write logits straight from accumulators ----
    float* lg = out + 4 * TOKENS;
    const int cbase = (lane & 3) * 2;
    #pragma unroll
    for (int nt = 0; nt < 8; nt++) {
        int c = nt * 8 + cbase;
        *(float2*)(lg + (size_t)r0 * NEXP + c)       = make_float2(acc[nt][0], acc[nt][1]);
        *(float2*)(lg + (size_t)(r0 + 8) * NEXP + c) = make_float2(acc[nt][2], acc[nt][3]);
    }

    // ---- per-row top-2 (register scan + quad shuffle merge) ----
    #pragma unroll
    for (int half = 0; half < 2; half++) {
        const int row = r0 + half * 8;
        float m1 = -INFINITY, m2 = -INFINITY;
        int i1 = 0, i2 = 0;
        #pragma unroll
        for (int nt = 0; nt < 8; nt++) {
            #pragma unroll
            for (int j = 0; j < 2; j++) {
                float v = acc[nt][half * 2 + j];
                int e = nt * 8 + cbase + j;
                if (v > m1)      { m2 = m1; i2 = i1; m1 = v; i1 = e; }
                else if (v > m2) { m2 = v; i2 = e; }
            }
        }
        // merge across the 4 quad lanes (they differ in low 2 bits of lane)
        #pragma unroll
        for (int d = 1; d < 4; d <<= 1) {
            float om1 = __shfl_xor_sync(0xFFFFFFFF, m1, d);
            int   oi1 = __shfl_xor_sync(0xFFFFFFFF, i1, d);
            float om2 = __shfl_xor_sync(0xFFFFFFFF, m2, d);
            int   oi2 = __shfl_xor_sync(0xFFFFFFFF, i2, d);
            if (better(om1, oi1, m1, i1)) {
                // other's top wins; second = better(my top, other's second)
                float nm2; int ni2;
                if (better(m1, i1, om2, oi2)) { nm2 = m1; ni2 = i1; }
                else                          { nm2 = om2; ni2 = oi2; }
                m1 = om1; i1 = oi1; m2 = nm2; i2 = ni2;
            } else {
                if (better(om1, oi1, m2, i2)) { m2 = om1; i2 = oi1; }
            }
        }
        if ((lane & 3) == 0) {
            // weights: full-softmax renorm of top-2 == 1/(1+e2), e2/(1+e2);
            // the reference's +1e-9 perturbs by <1e-7 relative -> negligible.
            float e2 = __expf(m2 - m1);
            float rcp = 1.0f / (1.0f + e2);
            out[(size_t)row * 2 + 0] = (float)i1;
            out[(size_t)row * 2 + 1] = (float)i2;
            out[2 * TOKENS + (size_t)row * 2 + 0] = rcp;
            out[2 * TOKENS + (size_t)row * 2 + 1] = e2 * rcp;
        }
    }
}

extern "C" void kernel_launch(void* const* d_in, const int* in_sizes, int n_in,
                              void* d_out, int out_size)
{
    const float* x  = (const float*)d_in[0];
    const float* Wg = (const float*)d_in[1];
    float* out = (float*)d_out;

    convert_w_kernel<<<256, 256>>>(Wg);
    router_kernel<<<TOKENS / 64, 128>>>(x, out);
}